// round 8
// baseline (speedup 1.0000x reference)
#include <cuda_runtime.h>
#include <cuda_bf16.h>
#include <cstdint>

#define D 128
#define ALPHA 0.5f
#define MAX_NODES 50000
#define MAX_EDGES 800000
#define NB 148            // persistent grid: <= SM count, all resident in wave 1
#define NT 256

// ---------------- scratch (static device globals; no allocation) ----------------
__device__ float g_y_src[(size_t)MAX_NODES * D];   // alpha * (x @ W_src)
__device__ float g_y_dst[(size_t)MAX_NODES * D];   // (1-alpha) * (x @ W_dst)
__device__ int   g_outdeg[MAX_NODES];
__device__ int   g_indeg[MAX_NODES];
__device__ float g_dout[MAX_NODES];
__device__ float g_din[MAX_NODES];
__device__ int   g_ei[2 * MAX_EDGES];

// software global barrier state (generation-based; self-resetting)
__device__ unsigned g_cnt = 0;
__device__ volatile unsigned g_gen = 0;

__device__ __forceinline__ void grid_barrier(int nblocks) {
    __syncthreads();
    if (threadIdx.x == 0) {
        unsigned my = g_gen;
        __threadfence();
        if (atomicAdd(&g_cnt, 1u) == (unsigned)(nblocks - 1)) {
            g_cnt = 0;
            __threadfence();
            g_gen = my + 1;
        } else {
            while (g_gen == my) { }
        }
        __threadfence();
    }
    __syncthreads();
}

// Dtype-agnostic index decode (exact for int32 and float32 encodings):
//  - int32 index in [0,n) -> first branch (float 0.0f has bits 0 -> also 0, correct)
//  - float-encoded index >= 1.0f: bits >= 0x3F800000, never < n as int -> reinterpret
__device__ __forceinline__ int decode_idx(int v, int n) {
    if ((unsigned)v < (unsigned)n) return v;
    float f = __int_as_float(v);
    int r = (f > 0.0f) ? (int)f : 0;
    return ((unsigned)r < (unsigned)n) ? r : 0;
}

#define GEMM_TR 64
#define GEMM_KT 32

__global__ void __launch_bounds__(NT)
fused_kernel(const float* __restrict__ x,
             const int* __restrict__ ei_raw,
             const float* __restrict__ W_src, const float* __restrict__ b_src,
             const float* __restrict__ W_dst, const float* __restrict__ b_dst,
             float* __restrict__ out,
             int N, int E) {
    __shared__ float Ws[GEMM_KT][D];        // 16 KB
    __shared__ float Xs[GEMM_TR][GEMM_KT];  // 8 KB

    const int tid = threadIdx.x;
    const int nb = gridDim.x;
    const int gstride = nb * NT;
    const int gtid = blockIdx.x * NT + tid;

    // ---------------- phase 1: bias -> out; zero degree counters ----------------
    for (int i = gtid; i < N * D; i += gstride) {
        int d = i & (D - 1);
        out[i] = ALPHA * b_src[d] + (1.0f - ALPHA) * b_dst[d];
    }
    for (int i = gtid; i < N; i += gstride) {
        g_outdeg[i] = 0;
        g_indeg[i] = 0;
    }
    grid_barrier(nb);

    // ---------------- phase 2a: decode edge index + count degrees ---------------
    for (int i = gtid; i < 2 * E; i += gstride) {
        int v = decode_idx(ei_raw[i], N);
        g_ei[i] = v;
        if (i < E) atomicAdd(&g_outdeg[v], 1);
        else       atomicAdd(&g_indeg[v], 1);
    }

    // ---------------- phase 2b: two GEMMs, tile jobs over blocks ----------------
    {
        const int tiles = (N + GEMM_TR - 1) / GEMM_TR;
        const int c  = tid & 31;
        const int rg = tid >> 5;
        for (int job = blockIdx.x; job < 2 * tiles; job += nb) {
            const bool is_src = (job < tiles);
            const float* W = is_src ? W_src : W_dst;
            float* Y       = is_src ? g_y_src : g_y_dst;
            const float scale = is_src ? ALPHA : (1.0f - ALPHA);
            const int row0 = (is_src ? job : job - tiles) * GEMM_TR;

            float acc[8][4];
#pragma unroll
            for (int j = 0; j < 8; j++)
#pragma unroll
                for (int q = 0; q < 4; q++) acc[j][q] = 0.0f;

            for (int kt = 0; kt < D; kt += GEMM_KT) {
#pragma unroll
                for (int i = tid; i < GEMM_KT * D; i += NT) {
                    int kk = i >> 7, dd = i & (D - 1);
                    Ws[kk][dd] = W[(kt + kk) * D + dd];
                }
#pragma unroll
                for (int i = tid; i < GEMM_TR * GEMM_KT; i += NT) {
                    int r = i / GEMM_KT, kk = i % GEMM_KT;
                    int gr = row0 + r;
                    Xs[r][kk] = (gr < N) ? x[(size_t)gr * D + kt + kk] : 0.0f;
                }
                __syncthreads();
#pragma unroll
                for (int k = 0; k < GEMM_KT; k++) {
                    float4 w4 = *(const float4*)&Ws[k][c * 4];
#pragma unroll
                    for (int j = 0; j < 8; j++) {
                        float xv = Xs[rg + 8 * j][k];
                        acc[j][0] += xv * w4.x;
                        acc[j][1] += xv * w4.y;
                        acc[j][2] += xv * w4.z;
                        acc[j][3] += xv * w4.w;
                    }
                }
                __syncthreads();
            }
#pragma unroll
            for (int j = 0; j < 8; j++) {
                int r = row0 + rg + 8 * j;
                if (r < N) {
                    float4 o = make_float4(scale * acc[j][0], scale * acc[j][1],
                                           scale * acc[j][2], scale * acc[j][3]);
                    *(float4*)&Y[(size_t)r * D + c * 4] = o;
                }
            }
        }
    }
    grid_barrier(nb);

    // ---------------- phase 3: inverse-sqrt degrees ------------------------------
    for (int i = gtid; i < N; i += gstride) {
        int od = g_outdeg[i];
        int id = g_indeg[i];
        g_dout[i] = (od > 0) ? rsqrtf((float)od) : 0.0f;
        g_din[i]  = (id > 0) ? rsqrtf((float)id) : 0.0f;
    }
    grid_barrier(nb);

    // ---------------- phase 4: fused bidirectional scatter (1 warp / edge) ------
    {
        const int lane = tid & 31;
        const int wpb = NT / 32;
        const int wstride = nb * wpb;
        const float4* ys = (const float4*)g_y_src;
        const float4* yd = (const float4*)g_y_dst;
        for (int e = blockIdx.x * wpb + (tid >> 5); e < E; e += wstride) {
            int row = g_ei[e];
            int col = g_ei[E + e];
            float w = g_dout[row] * g_din[col];

            float4 a = ys[col * 32 + lane];
            float4 b = yd[row * 32 + lane];

            float* po = out + (size_t)row * D + lane * 4;
            float* qo = out + (size_t)col * D + lane * 4;

            float ax = w * a.x, ay = w * a.y, az = w * a.z, aw = w * a.w;
            float bx = w * b.x, by = w * b.y, bz = w * b.z, bw = w * b.w;

            asm volatile("red.global.add.v4.f32 [%0], {%1, %2, %3, %4};"
                         :: "l"(po), "f"(ax), "f"(ay), "f"(az), "f"(aw) : "memory");
            asm volatile("red.global.add.v4.f32 [%0], {%1, %2, %3, %4};"
                         :: "l"(qo), "f"(bx), "f"(by), "f"(bz), "f"(bw) : "memory");
        }
    }
}

// ---------------- launch --------------------------------------------------------
extern "C" void kernel_launch(void* const* d_in, const int* in_sizes, int n_in,
                              void* d_out, int out_size) {
    // Size-based input identification (order-proof):
    //   x: out_size elems; W_*: 16384 (two); b_*: 128 (two); edge_index: the rest.
    // src/dst pairing: x before edge_index -> insertion order (src first),
    // otherwise sorted-key order (dst first).
    int idx_x = -1, idx_e = -1;
    int idxW[2] = {-1, -1}, idxB[2] = {-1, -1};
    int nw = 0, nb_ = 0;
    for (int i = 0; i < n_in; i++) {
        int s = in_sizes[i];
        if (s == out_size && idx_x < 0) idx_x = i;
        else if (s == D * D && nw < 2)  idxW[nw++] = i;
        else if (s == D && nb_ < 2)     idxB[nb_++] = i;
        else if (idx_e < 0)             idx_e = i;
    }
    bool src_first = (idx_x < idx_e);

    const float* x      = (const float*)d_in[idx_x];
    const int*   ei_raw = (const int*)d_in[idx_e];
    const float* W_src  = (const float*)d_in[src_first ? idxW[0] : idxW[1]];
    const float* W_dst  = (const float*)d_in[src_first ? idxW[1] : idxW[0]];
    const float* b_src  = (const float*)d_in[src_first ? idxB[0] : idxB[1]];
    const float* b_dst  = (const float*)d_in[src_first ? idxB[1] : idxB[0]];
    float* out = (float*)d_out;

    int N = out_size / D;            // 50000
    int E = in_sizes[idx_e] / 2;     // 800000
    if (E > MAX_EDGES) E = MAX_EDGES;

    // ONE launch, one graph node: all phases inside, separated by grid barriers.
    fused_kernel<<<NB, NT>>>(x, ei_raw, W_src, b_src, W_dst, b_dst, out, N, E);
}

// round 9
// speedup vs baseline: 2.1682x; 2.1682x over previous
#include <cuda_runtime.h>
#include <cuda_bf16.h>
#include <cstdint>

#define D 128
#define ALPHA 0.5f
#define MAX_NODES 50000
#define MAX_EDGES 800000
#define NB 296            // persistent grid: 2 CTAs/SM on 148 SMs, all co-resident
#define NT 256

// ---------------- scratch (static device globals; no allocation) ----------------
__device__ float g_y_src[(size_t)MAX_NODES * D];   // alpha * (x @ W_src)
__device__ float g_y_dst[(size_t)MAX_NODES * D];   // (1-alpha) * (x @ W_dst)
__device__ int   g_outdeg[MAX_NODES];
__device__ int   g_indeg[MAX_NODES];
__device__ float g_dout[MAX_NODES];
__device__ float g_din[MAX_NODES];
__device__ int   g_ei[2 * MAX_EDGES];

// software global barrier state (generation-based; self-resetting)
__device__ unsigned g_cnt = 0;
__device__ volatile unsigned g_gen = 0;

__device__ __forceinline__ void grid_barrier(int nblocks) {
    __syncthreads();
    if (threadIdx.x == 0) {
        unsigned my = g_gen;
        __threadfence();
        if (atomicAdd(&g_cnt, 1u) == (unsigned)(nblocks - 1)) {
            g_cnt = 0;
            __threadfence();
            g_gen = my + 1;
        } else {
            while (g_gen == my) { }
        }
        __threadfence();
    }
    __syncthreads();
}

// Dtype-agnostic index decode (exact for int32 and float32 encodings).
__device__ __forceinline__ int decode_idx(int v, int n) {
    if ((unsigned)v < (unsigned)n) return v;
    float f = __int_as_float(v);
    int r = (f > 0.0f) ? (int)f : 0;
    return ((unsigned)r < (unsigned)n) ? r : 0;
}

#define GEMM_TR 64
#define GEMM_KT 32

__global__ void __launch_bounds__(NT, 2)
fused_kernel(const float* __restrict__ x,
             const int* __restrict__ ei_raw,
             const float* __restrict__ W_src, const float* __restrict__ b_src,
             const float* __restrict__ W_dst, const float* __restrict__ b_dst,
             float* __restrict__ out,
             int N, int E) {
    __shared__ float Ws[GEMM_KT][D];        // 16 KB
    __shared__ float Xs[GEMM_TR][GEMM_KT];  // 8 KB

    const int tid = threadIdx.x;
    const int nb = gridDim.x;
    const int gstride = nb * NT;
    const int gtid = blockIdx.x * NT + tid;

    // ---------------- phase 1: bias -> out (float4); zero degree counters --------
    {
        float4 bias4[1];
        // each thread covers a fixed d-range pattern: i indexes float4 elements
        int total4 = N * (D / 4);
        for (int i = gtid; i < total4; i += gstride) {
            int d4 = i & (D / 4 - 1);
            int d = d4 * 4;
            bias4[0] = make_float4(
                ALPHA * b_src[d + 0] + (1.0f - ALPHA) * b_dst[d + 0],
                ALPHA * b_src[d + 1] + (1.0f - ALPHA) * b_dst[d + 1],
                ALPHA * b_src[d + 2] + (1.0f - ALPHA) * b_dst[d + 2],
                ALPHA * b_src[d + 3] + (1.0f - ALPHA) * b_dst[d + 3]);
            ((float4*)out)[i] = bias4[0];
        }
    }
    for (int i = gtid; i < N; i += gstride) {
        g_outdeg[i] = 0;
        g_indeg[i] = 0;
    }
    grid_barrier(nb);

    // ---------------- phase 2a: decode edge index + count degrees ----------------
    for (int i = gtid; i < 2 * E; i += gstride) {
        int v = decode_idx(ei_raw[i], N);
        g_ei[i] = v;
        if (i < E) atomicAdd(&g_outdeg[v], 1);
        else       atomicAdd(&g_indeg[v], 1);
    }

    // ---------------- phase 2b: two GEMMs, tile jobs over blocks -----------------
    {
        const int tiles = (N + GEMM_TR - 1) / GEMM_TR;
        const int c  = tid & 31;
        const int rg = tid >> 5;
        for (int job = blockIdx.x; job < 2 * tiles; job += nb) {
            const bool is_src = (job < tiles);
            const float* W = is_src ? W_src : W_dst;
            float* Y       = is_src ? g_y_src : g_y_dst;
            const float scale = is_src ? ALPHA : (1.0f - ALPHA);
            const int row0 = (is_src ? job : job - tiles) * GEMM_TR;

            float acc[8][4];
#pragma unroll
            for (int j = 0; j < 8; j++)
#pragma unroll
                for (int q = 0; q < 4; q++) acc[j][q] = 0.0f;

            for (int kt = 0; kt < D; kt += GEMM_KT) {
#pragma unroll
                for (int i = tid; i < GEMM_KT * D; i += NT) {
                    int kk = i >> 7, dd = i & (D - 1);
                    Ws[kk][dd] = W[(kt + kk) * D + dd];
                }
#pragma unroll
                for (int i = tid; i < GEMM_TR * GEMM_KT; i += NT) {
                    int r = i / GEMM_KT, kk = i % GEMM_KT;
                    int gr = row0 + r;
                    Xs[r][kk] = (gr < N) ? x[(size_t)gr * D + kt + kk] : 0.0f;
                }
                __syncthreads();
#pragma unroll
                for (int k = 0; k < GEMM_KT; k++) {
                    float4 w4 = *(const float4*)&Ws[k][c * 4];
#pragma unroll
                    for (int j = 0; j < 8; j++) {
                        float xv = Xs[rg + 8 * j][k];
                        acc[j][0] += xv * w4.x;
                        acc[j][1] += xv * w4.y;
                        acc[j][2] += xv * w4.z;
                        acc[j][3] += xv * w4.w;
                    }
                }
                __syncthreads();
            }
#pragma unroll
            for (int j = 0; j < 8; j++) {
                int r = row0 + rg + 8 * j;
                if (r < N) {
                    float4 o = make_float4(scale * acc[j][0], scale * acc[j][1],
                                           scale * acc[j][2], scale * acc[j][3]);
                    *(float4*)&Y[(size_t)r * D + c * 4] = o;
                }
            }
        }
    }
    grid_barrier(nb);

    // ---------------- phase 3: inverse-sqrt degrees ------------------------------
    for (int i = gtid; i < N; i += gstride) {
        int od = g_outdeg[i];
        int id = g_indeg[i];
        g_dout[i] = (od > 0) ? rsqrtf((float)od) : 0.0f;
        g_din[i]  = (id > 0) ? rsqrtf((float)id) : 0.0f;
    }
    grid_barrier(nb);

    // ---------------- phase 4: bidirectional scatter, 2 edges / warp-iter --------
    {
        const int lane = tid & 31;
        const int wpb = NT / 32;
        const int wid = blockIdx.x * wpb + (tid >> 5);
        const int wstride = nb * wpb;
        const float4* ys = (const float4*)g_y_src;
        const float4* yd = (const float4*)g_y_dst;

        // 2 edges per iteration: batch all 4 gathers before the 4 REDs (MLP=4+)
        int e = wid * 2;
        const int estep = wstride * 2;
        for (; e + 1 < E; e += estep) {
            int row0 = g_ei[e],     col0 = g_ei[E + e];
            int row1 = g_ei[e + 1], col1 = g_ei[E + e + 1];
            float w0 = g_dout[row0] * g_din[col0];
            float w1 = g_dout[row1] * g_din[col1];

            float4 a0 = ys[col0 * 32 + lane];
            float4 b0 = yd[row0 * 32 + lane];
            float4 a1 = ys[col1 * 32 + lane];
            float4 b1 = yd[row1 * 32 + lane];

            float* p0 = out + (size_t)row0 * D + lane * 4;
            float* q0 = out + (size_t)col0 * D + lane * 4;
            float* p1 = out + (size_t)row1 * D + lane * 4;
            float* q1 = out + (size_t)col1 * D + lane * 4;

            asm volatile("red.global.add.v4.f32 [%0], {%1, %2, %3, %4};"
                         :: "l"(p0), "f"(w0 * a0.x), "f"(w0 * a0.y),
                            "f"(w0 * a0.z), "f"(w0 * a0.w) : "memory");
            asm volatile("red.global.add.v4.f32 [%0], {%1, %2, %3, %4};"
                         :: "l"(q0), "f"(w0 * b0.x), "f"(w0 * b0.y),
                            "f"(w0 * b0.z), "f"(w0 * b0.w) : "memory");
            asm volatile("red.global.add.v4.f32 [%0], {%1, %2, %3, %4};"
                         :: "l"(p1), "f"(w1 * a1.x), "f"(w1 * a1.y),
                            "f"(w1 * a1.z), "f"(w1 * a1.w) : "memory");
            asm volatile("red.global.add.v4.f32 [%0], {%1, %2, %3, %4};"
                         :: "l"(q1), "f"(w1 * b1.x), "f"(w1 * b1.y),
                            "f"(w1 * b1.z), "f"(w1 * b1.w) : "memory");
        }
        // tail (at most one edge per warp)
        if (e < E) {
            int row = g_ei[e], col = g_ei[E + e];
            float w = g_dout[row] * g_din[col];
            float4 a = ys[col * 32 + lane];
            float4 b = yd[row * 32 + lane];
            float* po = out + (size_t)row * D + lane * 4;
            float* qo = out + (size_t)col * D + lane * 4;
            asm volatile("red.global.add.v4.f32 [%0], {%1, %2, %3, %4};"
                         :: "l"(po), "f"(w * a.x), "f"(w * a.y),
                            "f"(w * a.z), "f"(w * a.w) : "memory");
            asm volatile("red.global.add.v4.f32 [%0], {%1, %2, %3, %4};"
                         :: "l"(qo), "f"(w * b.x), "f"(w * b.y),
                            "f"(w * b.z), "f"(w * b.w) : "memory");
        }
    }
}

// ---------------- launch --------------------------------------------------------
extern "C" void kernel_launch(void* const* d_in, const int* in_sizes, int n_in,
                              void* d_out, int out_size) {
    // Size-based input identification (order-proof).
    int idx_x = -1, idx_e = -1;
    int idxW[2] = {-1, -1}, idxB[2] = {-1, -1};
    int nw = 0, nb_ = 0;
    for (int i = 0; i < n_in; i++) {
        int s = in_sizes[i];
        if (s == out_size && idx_x < 0) idx_x = i;
        else if (s == D * D && nw < 2)  idxW[nw++] = i;
        else if (s == D && nb_ < 2)     idxB[nb_++] = i;
        else if (idx_e < 0)             idx_e = i;
    }
    bool src_first = (idx_x < idx_e);

    const float* x      = (const float*)d_in[idx_x];
    const int*   ei_raw = (const int*)d_in[idx_e];
    const float* W_src  = (const float*)d_in[src_first ? idxW[0] : idxW[1]];
    const float* W_dst  = (const float*)d_in[src_first ? idxW[1] : idxW[0]];
    const float* b_src  = (const float*)d_in[src_first ? idxB[0] : idxB[1]];
    const float* b_dst  = (const float*)d_in[src_first ? idxB[1] : idxB[0]];
    float* out = (float*)d_out;

    int N = out_size / D;            // 50000
    int E = in_sizes[idx_e] / 2;     // 800000
    if (E > MAX_EDGES) E = MAX_EDGES;

    // ONE launch: all phases inside, separated by grid barriers.
    fused_kernel<<<NB, NT>>>(x, ei_raw, W_src, b_src, W_dst, b_dst, out, N, E);
}